// round 6
// baseline (speedup 1.0000x reference)
#include <cuda_runtime.h>
#include <cuda_bf16.h>
#include <cstdint>

#define N_NODES_MAX 50000
#define NODE_DIM    128
#define HIDDEN      256
#define NCOLS       1024

// Table column layout (permuted for edge locality):
//   [0:256)=seg0 (p1 row)  [256:512)=seg2 (p2 row)
//   [512:768)=seg1 (p1 col) [768:1024)=seg3 (p2 col)

__device__ __nv_bfloat16 g_table[(size_t)N_NODES_MAX * NCOLS];   // 102.4 MB
__device__ __nv_bfloat16 g_Xhi[(size_t)N_NODES_MAX * NODE_DIM];
__device__ __nv_bfloat16 g_Xlo[(size_t)N_NODES_MAX * NODE_DIM];
__device__ __nv_bfloat16 g_WThi[NCOLS * NODE_DIM];               // [n][k] permuted
__device__ float         g_c[HIDDEN];
__device__ int           g_is64;

__device__ __forceinline__ uint32_t smem_u32(const void* p) {
    uint32_t a;
    asm("{ .reg .u64 t; cvta.to.shared.u64 t, %1; cvt.u32.u64 %0, t; }" : "=r"(a) : "l"(p));
    return a;
}
__device__ __forceinline__ void ldsm_x4(uint32_t& r0, uint32_t& r1, uint32_t& r2, uint32_t& r3,
                                        uint32_t addr) {
    asm volatile("ldmatrix.sync.aligned.m8n8.x4.shared.b16 {%0,%1,%2,%3}, [%4];"
                 : "=r"(r0), "=r"(r1), "=r"(r2), "=r"(r3) : "r"(addr));
}
__device__ __forceinline__ void mma16816(float* c, const uint32_t* a, uint32_t b0, uint32_t b1) {
    asm volatile("mma.sync.aligned.m16n8k16.row.col.f32.bf16.bf16.f32 "
                 "{%0,%1,%2,%3}, {%4,%5,%6,%7}, {%8,%9}, {%0,%1,%2,%3};"
                 : "+f"(c[0]), "+f"(c[1]), "+f"(c[2]), "+f"(c[3])
                 : "r"(a[0]), "r"(a[1]), "r"(a[2]), "r"(a[3]), "r"(b0), "r"(b1));
}
#define CP16(dst, src) \
    asm volatile("cp.async.cg.shared.global [%0], [%1], 16;" :: "r"(dst), "l"(src))
#define CP16P(dst, src, p) \
    asm volatile("{ .reg .pred q; setp.ne.b32 q, %2, 0;\n\t" \
                 "@q cp.async.cg.shared.global [%0], [%1], 16; }" \
                 :: "r"(dst), "l"(src), "r"(p))
#define CP_COMMIT  asm volatile("cp.async.commit_group;")
#define CP_WAIT1   asm volatile("cp.async.wait_group 1;")

// ---------------------------------------------------------------------------
__global__ void detect_kernel(const int* __restrict__ idx32) {
    int lane = threadIdx.x;
    int acc = 0;
    for (int i = lane; i < 1024; i += 32) acc |= idx32[2 * i + 1];
    #pragma unroll
    for (int s = 16; s; s >>= 1) acc |= __shfl_xor_sync(0xFFFFFFFFu, acc, s);
    if (lane == 0) g_is64 = (acc == 0) ? 1 : 0;
}

// ---------------------------------------------------------------------------
__global__ void prep_w_kernel(const float* __restrict__ W1, const float* __restrict__ b1,
                              const float* __restrict__ gamma, const float* __restrict__ beta,
                              const float* __restrict__ mean, const float* __restrict__ var) {
    int i = blockIdx.x * blockDim.x + threadIdx.x;
    if (i < NCOLS * NODE_DIM) {
        int n = i >> 7;
        int k = i & 127;
        int h = n & 255;
        int grp = n >> 8;
        int srcRow;
        if (grp == 0)      srcRow = k;
        else if (grp == 1) srcRow = k + 16;
        else if (grp == 2) srcRow = 128 + k;
        else               srcRow = (k + 144) & 255;
        float s = gamma[h] * rsqrtf(var[h] + 1e-5f);
        g_WThi[i] = __float2bfloat16(W1[srcRow * 256 + h] * s);
    }
    if (i < HIDDEN) {
        float s = gamma[i] * rsqrtf(var[i] + 1e-5f);
        g_c[i] = b1[i] * s + beta[i] - mean[i] * s;
    }
}

__global__ void prep_x_kernel(const float* __restrict__ X, int total) {
    int i = blockIdx.x * blockDim.x + threadIdx.x;
    if (i >= total) return;
    float x = X[i];
    __nv_bfloat16 hi = __float2bfloat16(x);
    __nv_bfloat16 lo = __float2bfloat16(x - __bfloat162float(hi));
    g_Xhi[i] = hi;
    g_Xlo[i] = lo;
}

// ---------------------------------------------------------------------------
// Persistent warp-MMA bf16 GEMM, 2 passes (Ah*Bh + Al*Bh),
// K split into 2 chunks of 64 double-buffered -> 80KB smem, 2 CTAs/SM.
// ---------------------------------------------------------------------------
#define BM 128
#define BN 64
#define SM_B    0
#define SM_A    16384
#define A_STAGE 32768       // hi 16KB + lo 16KB per stage
#define SM_TOTAL 81920      // 16KB B + 2*32KB A

__global__ __launch_bounds__(256, 2) void gemm_mma_kernel(int M) {
    extern __shared__ char smem[];
    uint32_t sb = smem_u32(smem);
    int tid = threadIdx.x;
    int lane = tid & 31;
    int wid = tid >> 5;
    int wm = wid & 3;
    int wn = wid >> 2;
    int bn = blockIdx.x * BN;
    int y = blockIdx.y;
    int NY = gridDim.y;
    int totTiles = (M + BM - 1) / BM;

    // B tile (64 n-rows x 128 k), hi, swizzled (group 0)
    for (int s = tid; s < 1024; s += 256) {
        int row = s >> 4;
        int c = s & 15;
        uint32_t off = (uint32_t)(row * 256 + ((c ^ (row & 7)) << 4));
        CP16(sb + SM_B + off, (const char*)(g_WThi + (size_t)(bn + row) * 128 + c * 8));
    }
    CP_COMMIT;

    // prefetch one 64-k A chunk (hi+lo) into stage st
    auto prefetchChunk = [&](int t, int kc, int st) {
        int bm = t * BM;
        uint32_t base = sb + SM_A + st * A_STAGE;
        for (int s = tid; s < 1024; s += 256) {
            int row = s >> 3;
            int c = s & 7;
            int gr = bm + row;
            int valid = (gr < M) ? 1 : 0;
            uint32_t off = (uint32_t)(row * 128 + ((c ^ (row & 7)) << 4));
            CP16P(base + off,         (const char*)(g_Xhi + (size_t)gr * 128 + kc * 64 + c * 8), valid);
            CP16P(base + 16384 + off, (const char*)(g_Xlo + (size_t)gr * 128 + kc * 64 + c * 8), valid);
        }
        CP_COMMIT;
    };

    if (y < totTiles) prefetchChunk(y, 0, 0); else CP_COMMIT;

    int aR = (lane & 15);
    int aC = lane >> 4;
    int bR = (lane & 7) + ((lane >> 4) << 3);
    int bC = (lane >> 3) & 1;

    float acc[2][4][4];
    int i = 0;
    for (int t = y; t < totTiles; t += NY) {
        #pragma unroll 1
        for (int kc = 0; kc < 2; kc++, i++) {
            // prefetch next chunk (stage just freed by the sync at end of prev item)
            int nt = t, nkc = kc + 1;
            if (nkc == 2) { nkc = 0; nt = t + NY; }
            if (nt < totTiles) prefetchChunk(nt, nkc, (i + 1) & 1); else CP_COMMIT;
            CP_WAIT1;
            __syncthreads();

            if (kc == 0) {
                #pragma unroll
                for (int mt = 0; mt < 2; mt++)
                    #pragma unroll
                    for (int nt2 = 0; nt2 < 4; nt2++)
                        #pragma unroll
                        for (int q = 0; q < 4; q++) acc[mt][nt2][q] = 0.f;
            }

            uint32_t aBase = sb + SM_A + (i & 1) * A_STAGE;
            #pragma unroll
            for (int ks = 0; ks < 4; ks++) {
                uint32_t ah[2][4], al[2][4], bh[2][4];
                #pragma unroll
                for (int mt = 0; mt < 2; mt++) {
                    int row = wm * 32 + mt * 16 + aR;
                    int ch = ks * 2 + aC;
                    uint32_t off = (uint32_t)(row * 128 + ((ch ^ (row & 7)) << 4));
                    ldsm_x4(ah[mt][0], ah[mt][1], ah[mt][2], ah[mt][3], aBase + off);
                    ldsm_x4(al[mt][0], al[mt][1], al[mt][2], al[mt][3], aBase + 16384 + off);
                }
                #pragma unroll
                for (int np = 0; np < 2; np++) {
                    int row = wn * 32 + np * 16 + bR;
                    int chb = kc * 8 + ks * 2 + bC;
                    uint32_t off = (uint32_t)(row * 256 + ((chb ^ (row & 7)) << 4));
                    ldsm_x4(bh[np][0], bh[np][1], bh[np][2], bh[np][3], sb + SM_B + off);
                }
                #pragma unroll
                for (int mt = 0; mt < 2; mt++)
                    #pragma unroll
                    for (int nt2 = 0; nt2 < 4; nt2++) {
                        int hp = nt2 >> 1, qp = (nt2 & 1) * 2;
                        mma16816(acc[mt][nt2], ah[mt], bh[hp][qp], bh[hp][qp + 1]);
                        mma16816(acc[mt][nt2], al[mt], bh[hp][qp], bh[hp][qp + 1]);
                    }
            }

            if (kc == 1) {
                int bm = t * BM;
                #pragma unroll
                for (int mt = 0; mt < 2; mt++) {
                    #pragma unroll
                    for (int h = 0; h < 2; h++) {
                        int row = bm + wm * 32 + mt * 16 + (lane >> 2) + h * 8;
                        if (row < M) {
                            __nv_bfloat16* dst = g_table + (size_t)row * NCOLS + bn + wn * 32 + (lane & 3) * 2;
                            #pragma unroll
                            for (int nt2 = 0; nt2 < 4; nt2++)
                                *(__nv_bfloat162*)(dst + nt2 * 8) =
                                    __floats2bfloat162_rn(acc[mt][nt2][h * 2], acc[mt][nt2][h * 2 + 1]);
                        }
                    }
                }
            }
            __syncthreads();   // compute done before this stage is re-prefetched
        }
    }
}

// ---------------------------------------------------------------------------
// Edge kernel: warp handles 2 edges; 2 contiguous 1KB streams per edge.
// ---------------------------------------------------------------------------
__global__ __launch_bounds__(256) void edge_kernel(const void* __restrict__ idx,
                                                   const float* __restrict__ W2,
                                                   const float* __restrict__ b2,
                                                   float* __restrict__ out, int E) {
    int lane = threadIdx.x & 31;
    int e0 = blockIdx.x * 16 + (threadIdx.x >> 5) * 2;
    if (e0 >= E) return;
    bool has2 = (e0 + 1 < E);
    int o = lane * 8;

    int r0, c0, r1 = 0, c1 = 0;
    if (g_is64) {
        const long long* p = (const long long*)idx;
        r0 = (int)p[e0]; c0 = (int)p[E + e0];
        if (has2) { r1 = (int)p[e0 + 1]; c1 = (int)p[E + e0 + 1]; }
    } else {
        const int* p = (const int*)idx;
        r0 = p[e0]; c0 = p[E + e0];
        if (has2) { r1 = p[e0 + 1]; c1 = p[E + e0 + 1]; }
    }

    const __nv_bfloat16* Tr0 = g_table + (size_t)r0 * NCOLS;
    const __nv_bfloat16* Tc0 = g_table + (size_t)c0 * NCOLS;
    const __nv_bfloat16* Tr1 = g_table + (size_t)(has2 ? r1 : r0) * NCOLS;
    const __nv_bfloat16* Tc1 = g_table + (size_t)(has2 ? c1 : c0) * NCOLS;

    uint4 a0 = *(const uint4*)(Tr0 + o);
    uint4 a2 = *(const uint4*)(Tr0 + 256 + o);
    uint4 b1 = *(const uint4*)(Tc0 + 512 + o);
    uint4 b3 = *(const uint4*)(Tc0 + 768 + o);
    uint4 d0 = *(const uint4*)(Tr1 + o);
    uint4 d2 = *(const uint4*)(Tr1 + 256 + o);
    uint4 e1v = *(const uint4*)(Tc1 + 512 + o);
    uint4 e3 = *(const uint4*)(Tc1 + 768 + o);

    float cc[8], ww[8];
    *(float4*)(cc)     = *(const float4*)(g_c + o);
    *(float4*)(cc + 4) = *(const float4*)(g_c + o + 4);
    *(float4*)(ww)     = *(const float4*)(W2 + o);
    *(float4*)(ww + 4) = *(const float4*)(W2 + o + 4);

    const uint32_t* pa0 = &a0.x; const uint32_t* pa2 = &a2.x;
    const uint32_t* pb1 = &b1.x; const uint32_t* pb3 = &b3.x;
    const uint32_t* pd0 = &d0.x; const uint32_t* pd2 = &d2.x;
    const uint32_t* pe1 = &e1v.x; const uint32_t* pe3 = &e3.x;

    float accA = 0.f, accB = 0.f;
    #pragma unroll
    for (int j = 0; j < 4; j++) {
        float2 fa0 = __bfloat1622float2(*reinterpret_cast<const __nv_bfloat162*>(&pa0[j]));
        float2 fb1 = __bfloat1622float2(*reinterpret_cast<const __nv_bfloat162*>(&pb1[j]));
        float2 fa2 = __bfloat1622float2(*reinterpret_cast<const __nv_bfloat162*>(&pa2[j]));
        float2 fb3 = __bfloat1622float2(*reinterpret_cast<const __nv_bfloat162*>(&pb3[j]));
        float2 fd0 = __bfloat1622float2(*reinterpret_cast<const __nv_bfloat162*>(&pd0[j]));
        float2 fe1 = __bfloat1622float2(*reinterpret_cast<const __nv_bfloat162*>(&pe1[j]));
        float2 fd2 = __bfloat1622float2(*reinterpret_cast<const __nv_bfloat162*>(&pd2[j]));
        float2 fe3 = __bfloat1622float2(*reinterpret_cast<const __nv_bfloat162*>(&pe3[j]));
        float cx = cc[j * 2], cy = cc[j * 2 + 1];
        float wx = ww[j * 2], wy = ww[j * 2 + 1];
        accA += fmaxf(fa0.x + fb1.x + cx, 0.f) * wx;
        accA += fmaxf(fa0.y + fb1.y + cy, 0.f) * wy;
        accA += fmaxf(fa2.x + fb3.x + cx, 0.f) * wx;
        accA += fmaxf(fa2.y + fb3.y + cy, 0.f) * wy;
        accB += fmaxf(fd0.x + fe1.x + cx, 0.f) * wx;
        accB += fmaxf(fd0.y + fe1.y + cy, 0.f) * wy;
        accB += fmaxf(fd2.x + fe3.x + cx, 0.f) * wx;
        accB += fmaxf(fd2.y + fe3.y + cy, 0.f) * wy;
    }
    #pragma unroll
    for (int s = 16; s; s >>= 1) {
        accA += __shfl_xor_sync(0xFFFFFFFFu, accA, s);
        accB += __shfl_xor_sync(0xFFFFFFFFu, accB, s);
    }

    if (lane == 0) {
        float x = accA * 0.5f + b2[0];
        out[e0] = 1.f / (1.f + expf(-x));
        if (has2) {
            float x2 = accB * 0.5f + b2[0];
            out[e0 + 1] = 1.f / (1.f + expf(-x2));
        }
    }
}

// ---------------------------------------------------------------------------
extern "C" void kernel_launch(void* const* d_in, const int* in_sizes, int n_in,
                              void* d_out, int out_size) {
    const float* node_feat = (const float*)d_in[0];
    const void*  eidx      = d_in[1];
    const float* W1        = (const float*)d_in[2];
    const float* b1        = (const float*)d_in[3];
    const float* gamma     = (const float*)d_in[4];
    const float* beta      = (const float*)d_in[5];
    const float* mean      = (const float*)d_in[6];
    const float* var       = (const float*)d_in[7];
    const float* W2        = (const float*)d_in[8];
    const float* b2        = (const float*)d_in[9];
    float* out = (float*)d_out;

    int M = in_sizes[0] / NODE_DIM;   // 50000
    int E = out_size;                 // 300000

    cudaFuncSetAttribute(gemm_mma_kernel, cudaFuncAttributeMaxDynamicSharedMemorySize, SM_TOTAL);

    detect_kernel<<<1, 32>>>((const int*)eidx);
    prep_w_kernel<<<(NCOLS * NODE_DIM + 255) / 256, 256>>>(W1, b1, gamma, beta, mean, var);
    prep_x_kernel<<<(M * NODE_DIM + 255) / 256, 256>>>(node_feat, M * NODE_DIM);

    dim3 ggrid(NCOLS / BN, 18);   // 288 persistent CTAs, 2/SM
    gemm_mma_kernel<<<ggrid, 256, SM_TOTAL>>>(M);

    edge_kernel<<<(E + 15) / 16, 256>>>(eidx, W2, b2, out, E);
}

// round 7
// speedup vs baseline: 1.0477x; 1.0477x over previous
#include <cuda_runtime.h>
#include <cuda_fp16.h>
#include <cstdint>

#define N_NODES_MAX 50000
#define NODE_DIM    128
#define HIDDEN      256
#define NCOLS       1024

// Table column layout (permuted for edge locality):
//   [0:256)=seg0 (p1 row)  [256:512)=seg2 (p2 row)
//   [512:768)=seg1 (p1 col) [768:1024)=seg3 (p2 col)

__device__ __half g_table[(size_t)N_NODES_MAX * NCOLS];   // 102.4 MB
__device__ __half g_Xh[(size_t)N_NODES_MAX * NODE_DIM];   // 12.8 MB
__device__ __half g_WTh[NCOLS * NODE_DIM];                // [n][k] permuted
__device__ float  g_c[HIDDEN];
__device__ int    g_is64;

__device__ __forceinline__ uint32_t smem_u32(const void* p) {
    uint32_t a;
    asm("{ .reg .u64 t; cvta.to.shared.u64 t, %1; cvt.u32.u64 %0, t; }" : "=r"(a) : "l"(p));
    return a;
}
__device__ __forceinline__ void ldsm_x4(uint32_t& r0, uint32_t& r1, uint32_t& r2, uint32_t& r3,
                                        uint32_t addr) {
    asm volatile("ldmatrix.sync.aligned.m8n8.x4.shared.b16 {%0,%1,%2,%3}, [%4];"
                 : "=r"(r0), "=r"(r1), "=r"(r2), "=r"(r3) : "r"(addr));
}
__device__ __forceinline__ void mma16816(float* c, const uint32_t* a, uint32_t b0, uint32_t b1) {
    asm volatile("mma.sync.aligned.m16n8k16.row.col.f32.f16.f16.f32 "
                 "{%0,%1,%2,%3}, {%4,%5,%6,%7}, {%8,%9}, {%0,%1,%2,%3};"
                 : "+f"(c[0]), "+f"(c[1]), "+f"(c[2]), "+f"(c[3])
                 : "r"(a[0]), "r"(a[1]), "r"(a[2]), "r"(a[3]), "r"(b0), "r"(b1));
}
#define CP16(dst, src) \
    asm volatile("cp.async.cg.shared.global [%0], [%1], 16;" :: "r"(dst), "l"(src))
#define CP16P(dst, src, p) \
    asm volatile("{ .reg .pred q; setp.ne.b32 q, %2, 0;\n\t" \
                 "@q cp.async.cg.shared.global [%0], [%1], 16; }" \
                 :: "r"(dst), "l"(src), "r"(p))
#define CP_COMMIT  asm volatile("cp.async.commit_group;")
#define CP_WAIT1   asm volatile("cp.async.wait_group 1;")

// ---------------------------------------------------------------------------
__global__ void detect_kernel(const int* __restrict__ idx32) {
    int lane = threadIdx.x;
    int acc = 0;
    for (int i = lane; i < 1024; i += 32) acc |= idx32[2 * i + 1];
    #pragma unroll
    for (int s = 16; s; s >>= 1) acc |= __shfl_xor_sync(0xFFFFFFFFu, acc, s);
    if (lane == 0) g_is64 = (acc == 0) ? 1 : 0;
}

// ---------------------------------------------------------------------------
// prep: folded transposed weights (fp16) + bias constant, PERMUTED:
//   grp0 -> srcRow=k        grp1 -> srcRow=k+16
//   grp2 -> srcRow=128+k    grp3 -> srcRow=(k+144)&255
// ---------------------------------------------------------------------------
__global__ void prep_w_kernel(const float* __restrict__ W1, const float* __restrict__ b1,
                              const float* __restrict__ gamma, const float* __restrict__ beta,
                              const float* __restrict__ mean, const float* __restrict__ var) {
    int i = blockIdx.x * blockDim.x + threadIdx.x;
    if (i < NCOLS * NODE_DIM) {
        int n = i >> 7;
        int k = i & 127;
        int h = n & 255;
        int grp = n >> 8;
        int srcRow;
        if (grp == 0)      srcRow = k;
        else if (grp == 1) srcRow = k + 16;
        else if (grp == 2) srcRow = 128 + k;
        else               srcRow = (k + 144) & 255;
        float s = gamma[h] * rsqrtf(var[h] + 1e-5f);
        g_WTh[i] = __float2half_rn(W1[srcRow * 256 + h] * s);
    }
    if (i < HIDDEN) {
        float s = gamma[i] * rsqrtf(var[i] + 1e-5f);
        g_c[i] = b1[i] * s + beta[i] - mean[i] * s;
    }
}

__global__ void prep_x_kernel(const float* __restrict__ X, int total4) {
    int i = blockIdx.x * blockDim.x + threadIdx.x;
    if (i >= total4) return;
    float4 v = *(const float4*)(X + i * 4);
    __half2* dst = (__half2*)(g_Xh + i * 4);
    dst[0] = __floats2half2_rn(v.x, v.y);
    dst[1] = __floats2half2_rn(v.z, v.w);
}

// ---------------------------------------------------------------------------
// Persistent warp-MMA fp16 GEMM (single pass): table[M x 1024] = X @ WT^T
// Full-K (128) A tiles, double-buffered; B resident. 80KB smem, 2 CTAs/SM.
// ---------------------------------------------------------------------------
#define BM 128
#define BN 64
#define SM_B    0
#define SM_A    16384
#define A_STAGE 32768
#define SM_TOTAL 81920     // 16KB B + 2*32KB A

__global__ __launch_bounds__(256, 2) void gemm_mma_kernel(int M) {
    extern __shared__ char smem[];
    uint32_t sb = smem_u32(smem);
    int tid = threadIdx.x;
    int lane = tid & 31;
    int wid = tid >> 5;
    int wm = wid & 3;
    int wn = wid >> 2;
    int bn = blockIdx.x * BN;
    int y = blockIdx.y;
    int NY = gridDim.y;
    int totTiles = (M + BM - 1) / BM;

    // B tile (64 n-rows x 128 k) swizzled (group 0)
    for (int s = tid; s < 1024; s += 256) {
        int row = s >> 4;
        int c = s & 15;
        uint32_t off = (uint32_t)(row * 256 + ((c ^ (row & 7)) << 4));
        CP16(sb + SM_B + off, (const char*)(g_WTh + (size_t)(bn + row) * 128 + c * 8));
    }
    CP_COMMIT;

    auto prefetchA = [&](int t, int st) {
        int bm = t * BM;
        uint32_t base = sb + SM_A + st * A_STAGE;
        for (int s = tid; s < 2048; s += 256) {
            int row = s >> 4;
            int c = s & 15;
            int gr = bm + row;
            int valid = (gr < M) ? 1 : 0;
            uint32_t off = (uint32_t)(row * 256 + ((c ^ (row & 7)) << 4));
            CP16P(base + off, (const char*)(g_Xh + (size_t)gr * 128 + c * 8), valid);
        }
        CP_COMMIT;
    };

    if (y < totTiles) prefetchA(y, 0); else CP_COMMIT;

    int aR = (lane & 15);
    int aC = lane >> 4;
    int bR = (lane & 7) + ((lane >> 4) << 3);
    int bC = (lane >> 3) & 1;

    int i = 0;
    for (int t = y; t < totTiles; t += NY, i++) {
        int tn = t + NY;
        if (tn < totTiles) prefetchA(tn, (i + 1) & 1); else CP_COMMIT;
        CP_WAIT1;
        __syncthreads();

        uint32_t aBase = sb + SM_A + (i & 1) * A_STAGE;

        float acc[2][4][4];
        #pragma unroll
        for (int mt = 0; mt < 2; mt++)
            #pragma unroll
            for (int nt = 0; nt < 4; nt++)
                #pragma unroll
                for (int q = 0; q < 4; q++) acc[mt][nt][q] = 0.f;

        #pragma unroll
        for (int ks = 0; ks < 8; ks++) {
            uint32_t a[2][4], b[2][4];
            #pragma unroll
            for (int mt = 0; mt < 2; mt++) {
                int row = wm * 32 + mt * 16 + aR;
                int ch = ks * 2 + aC;
                uint32_t off = (uint32_t)(row * 256 + ((ch ^ (row & 7)) << 4));
                ldsm_x4(a[mt][0], a[mt][1], a[mt][2], a[mt][3], aBase + off);
            }
            #pragma unroll
            for (int np = 0; np < 2; np++) {
                int row = wn * 32 + np * 16 + bR;
                int ch = ks * 2 + bC;
                uint32_t off = (uint32_t)(row * 256 + ((ch ^ (row & 7)) << 4));
                ldsm_x4(b[np][0], b[np][1], b[np][2], b[np][3], sb + SM_B + off);
            }
            #pragma unroll
            for (int mt = 0; mt < 2; mt++)
                #pragma unroll
                for (int nt = 0; nt < 4; nt++) {
                    int hp = nt >> 1, qp = (nt & 1) * 2;
                    mma16816(acc[mt][nt], a[mt], b[hp][qp], b[hp][qp + 1]);
                }
        }

        int bm = t * BM;
        #pragma unroll
        for (int mt = 0; mt < 2; mt++) {
            #pragma unroll
            for (int h = 0; h < 2; h++) {
                int row = bm + wm * 32 + mt * 16 + (lane >> 2) + h * 8;
                if (row < M) {
                    __half* dst = g_table + (size_t)row * NCOLS + bn + wn * 32 + (lane & 3) * 2;
                    #pragma unroll
                    for (int nt = 0; nt < 4; nt++)
                        *(__half2*)(dst + nt * 8) =
                            __floats2half2_rn(acc[mt][nt][h * 2], acc[mt][nt][h * 2 + 1]);
                }
            }
        }
        __syncthreads();
    }
}

// ---------------------------------------------------------------------------
// Edge kernel: warp handles 4 edges -> 16 outstanding 16B gathers.
// ---------------------------------------------------------------------------
__global__ __launch_bounds__(256) void edge_kernel(const void* __restrict__ idx,
                                                   const float* __restrict__ W2,
                                                   const float* __restrict__ b2,
                                                   float* __restrict__ out, int E) {
    int lane = threadIdx.x & 31;
    int e0 = blockIdx.x * 32 + (threadIdx.x >> 5) * 4;
    if (e0 >= E) return;
    int o = lane * 8;

    int r[4], c[4];
    if (g_is64) {
        const long long* p = (const long long*)idx;
        #pragma unroll
        for (int q = 0; q < 4; q++) {
            int e = min(e0 + q, E - 1);
            r[q] = (int)p[e]; c[q] = (int)p[E + e];
        }
    } else {
        const int* p = (const int*)idx;
        #pragma unroll
        for (int q = 0; q < 4; q++) {
            int e = min(e0 + q, E - 1);
            r[q] = p[e]; c[q] = p[E + e];
        }
    }

    uint4 rv0[4], rv2[4], cv1[4], cv3[4];
    #pragma unroll
    for (int q = 0; q < 4; q++) {
        const __half* Tr = g_table + (size_t)r[q] * NCOLS;
        const __half* Tc = g_table + (size_t)c[q] * NCOLS;
        rv0[q] = *(const uint4*)(Tr + o);
        rv2[q] = *(const uint4*)(Tr + 256 + o);
        cv1[q] = *(const uint4*)(Tc + 512 + o);
        cv3[q] = *(const uint4*)(Tc + 768 + o);
    }

    float cc[8], ww[8];
    *(float4*)(cc)     = *(const float4*)(g_c + o);
    *(float4*)(cc + 4) = *(const float4*)(g_c + o + 4);
    *(float4*)(ww)     = *(const float4*)(W2 + o);
    *(float4*)(ww + 4) = *(const float4*)(W2 + o + 4);

    float acc[4] = {0.f, 0.f, 0.f, 0.f};
    #pragma unroll
    for (int q = 0; q < 4; q++) {
        const uint32_t* p0 = &rv0[q].x;
        const uint32_t* p2 = &rv2[q].x;
        const uint32_t* p1 = &cv1[q].x;
        const uint32_t* p3 = &cv3[q].x;
        #pragma unroll
        for (int j = 0; j < 4; j++) {
            float2 f0 = __half22float2(*reinterpret_cast<const __half2*>(&p0[j]));
            float2 f1 = __half22float2(*reinterpret_cast<const __half2*>(&p1[j]));
            float2 f2 = __half22float2(*reinterpret_cast<const __half2*>(&p2[j]));
            float2 f3 = __half22float2(*reinterpret_cast<const __half2*>(&p3[j]));
            float cx = cc[j * 2], cy = cc[j * 2 + 1];
            float wx = ww[j * 2], wy = ww[j * 2 + 1];
            acc[q] += fmaxf(f0.x + f1.x + cx, 0.f) * wx;
            acc[q] += fmaxf(f0.y + f1.y + cy, 0.f) * wy;
            acc[q] += fmaxf(f2.x + f3.x + cx, 0.f) * wx;
            acc[q] += fmaxf(f2.y + f3.y + cy, 0.f) * wy;
        }
    }
    #pragma unroll
    for (int s = 16; s; s >>= 1) {
        #pragma unroll
        for (int q = 0; q < 4; q++)
            acc[q] += __shfl_xor_sync(0xFFFFFFFFu, acc[q], s);
    }

    if (lane == 0) {
        float bb = b2[0];
        #pragma unroll
        for (int q = 0; q < 4; q++) {
            int e = e0 + q;
            if (e < E) {
                float x = acc[q] * 0.5f + bb;
                out[e] = 1.f / (1.f + expf(-x));
            }
        }
    }
}

// ---------------------------------------------------------------------------
extern "C" void kernel_launch(void* const* d_in, const int* in_sizes, int n_in,
                              void* d_out, int out_size) {
    const float* node_feat = (const float*)d_in[0];
    const void*  eidx      = d_in[1];
    const float* W1        = (const float*)d_in[2];
    const float* b1        = (const float*)d_in[3];
    const float* gamma     = (const float*)d_in[4];
    const float* beta      = (const float*)d_in[5];
    const float* mean      = (const float*)d_in[6];
    const float* var       = (const float*)d_in[7];
    const float* W2        = (const float*)d_in[8];
    const float* b2        = (const float*)d_in[9];
    float* out = (float*)d_out;

    int M = in_sizes[0] / NODE_DIM;   // 50000
    int E = out_size;                 // 300000

    cudaFuncSetAttribute(gemm_mma_kernel, cudaFuncAttributeMaxDynamicSharedMemorySize, SM_TOTAL);

    detect_kernel<<<1, 32>>>((const int*)eidx);
    prep_w_kernel<<<(NCOLS * NODE_DIM + 255) / 256, 256>>>(W1, b1, gamma, beta, mean, var);
    prep_x_kernel<<<(M * NODE_DIM / 4 + 255) / 256, 256>>>(node_feat, M * NODE_DIM / 4);

    dim3 ggrid(NCOLS / BN, 18);   // 288 persistent CTAs, 2/SM
    gemm_mma_kernel<<<ggrid, 256, SM_TOTAL>>>(M);

    edge_kernel<<<(E + 31) / 32, 256>>>(eidx, W2, b2, out, E);
}

// round 8
// speedup vs baseline: 1.2721x; 1.2142x over previous
#include <cuda_runtime.h>
#include <cuda_fp16.h>
#include <cstdint>

#define N_NODES_MAX 50000
#define NODE_DIM    128
#define HIDDEN      256
#define NCOLS       1024

// Table column layout (permuted for edge locality):
//   [0:256)=seg0 (p1 row)  [256:512)=seg2 (p2 row)
//   [512:768)=seg1 (p1 col) [768:1024)=seg3 (p2 col)

__device__ __half g_table[(size_t)N_NODES_MAX * NCOLS];   // 102.4 MB
__device__ __half g_Xh[(size_t)N_NODES_MAX * NODE_DIM];   // 12.8 MB
__device__ __half g_WTh[NCOLS * NODE_DIM];                // [n][k] permuted
__device__ float  g_c[HIDDEN];
__device__ int    g_is64;

__device__ __forceinline__ uint32_t smem_u32(const void* p) {
    uint32_t a;
    asm("{ .reg .u64 t; cvta.to.shared.u64 t, %1; cvt.u32.u64 %0, t; }" : "=r"(a) : "l"(p));
    return a;
}
__device__ __forceinline__ void ldsm_x4(uint32_t& r0, uint32_t& r1, uint32_t& r2, uint32_t& r3,
                                        uint32_t addr) {
    asm volatile("ldmatrix.sync.aligned.m8n8.x4.shared.b16 {%0,%1,%2,%3}, [%4];"
                 : "=r"(r0), "=r"(r1), "=r"(r2), "=r"(r3) : "r"(addr));
}
__device__ __forceinline__ void mma16816(float* c, const uint32_t* a, uint32_t b0, uint32_t b1) {
    asm volatile("mma.sync.aligned.m16n8k16.row.col.f32.f16.f16.f32 "
                 "{%0,%1,%2,%3}, {%4,%5,%6,%7}, {%8,%9}, {%0,%1,%2,%3};"
                 : "+f"(c[0]), "+f"(c[1]), "+f"(c[2]), "+f"(c[3])
                 : "r"(a[0]), "r"(a[1]), "r"(a[2]), "r"(a[3]), "r"(b0), "r"(b1));
}
#define CP16(dst, src) \
    asm volatile("cp.async.cg.shared.global [%0], [%1], 16;" :: "r"(dst), "l"(src))
#define CP16P(dst, src, p) \
    asm volatile("{ .reg .pred q; setp.ne.b32 q, %2, 0;\n\t" \
                 "@q cp.async.cg.shared.global [%0], [%1], 16; }" \
                 :: "r"(dst), "l"(src), "r"(p))
#define CP_COMMIT  asm volatile("cp.async.commit_group;")
#define CP_WAIT1   asm volatile("cp.async.wait_group 1;")

// ---------------------------------------------------------------------------
__global__ void detect_kernel(const int* __restrict__ idx32) {
    int lane = threadIdx.x;
    int acc = 0;
    for (int i = lane; i < 1024; i += 32) acc |= idx32[2 * i + 1];
    #pragma unroll
    for (int s = 16; s; s >>= 1) acc |= __shfl_xor_sync(0xFFFFFFFFu, acc, s);
    if (lane == 0) g_is64 = (acc == 0) ? 1 : 0;
}

// ---------------------------------------------------------------------------
__global__ void prep_w_kernel(const float* __restrict__ W1, const float* __restrict__ b1,
                              const float* __restrict__ gamma, const float* __restrict__ beta,
                              const float* __restrict__ mean, const float* __restrict__ var) {
    int i = blockIdx.x * blockDim.x + threadIdx.x;
    if (i < NCOLS * NODE_DIM) {
        int n = i >> 7;
        int k = i & 127;
        int h = n & 255;
        int grp = n >> 8;
        int srcRow;
        if (grp == 0)      srcRow = k;
        else if (grp == 1) srcRow = k + 16;
        else if (grp == 2) srcRow = 128 + k;
        else               srcRow = (k + 144) & 255;
        float s = gamma[h] * rsqrtf(var[h] + 1e-5f);
        g_WTh[i] = __float2half_rn(W1[srcRow * 256 + h] * s);
    }
    if (i < HIDDEN) {
        float s = gamma[i] * rsqrtf(var[i] + 1e-5f);
        g_c[i] = b1[i] * s + beta[i] - mean[i] * s;
    }
}

__global__ void prep_x_kernel(const float* __restrict__ X, int total4) {
    int i = blockIdx.x * blockDim.x + threadIdx.x;
    if (i >= total4) return;
    float4 v = *(const float4*)(X + i * 4);
    __half2* dst = (__half2*)(g_Xh + i * 4);
    dst[0] = __floats2half2_rn(v.x, v.y);
    dst[1] = __floats2half2_rn(v.z, v.w);
}

// ---------------------------------------------------------------------------
// Persistent warp-MMA fp16 GEMM: B fragments hoisted to registers (loaded
// once per CTA), A tiles double-buffered via cp.async. 80KB smem.
// ---------------------------------------------------------------------------
#define BM 128
#define BN 64
#define SM_B    0
#define SM_A    16384
#define A_STAGE 32768
#define SM_TOTAL 81920

__global__ __launch_bounds__(256, 1) void gemm_mma_kernel(int M) {
    extern __shared__ char smem[];
    uint32_t sb = smem_u32(smem);
    int tid = threadIdx.x;
    int lane = tid & 31;
    int wid = tid >> 5;
    int wm = wid & 3;
    int wn = wid >> 2;
    int bn = blockIdx.x * BN;
    int y = blockIdx.y;
    int NY = gridDim.y;
    int totTiles = (M + BM - 1) / BM;

    // B tile (64 n-rows x 128 k) swizzled (group 0)
    for (int s = tid; s < 1024; s += 256) {
        int row = s >> 4;
        int c = s & 15;
        uint32_t off = (uint32_t)(row * 256 + ((c ^ (row & 7)) << 4));
        CP16(sb + SM_B + off, (const char*)(g_WTh + (size_t)(bn + row) * 128 + c * 8));
    }
    CP_COMMIT;

    auto prefetchA = [&](int t, int st) {
        int bm = t * BM;
        uint32_t base = sb + SM_A + st * A_STAGE;
        for (int s = tid; s < 2048; s += 256) {
            int row = s >> 4;
            int c = s & 15;
            int gr = bm + row;
            int valid = (gr < M) ? 1 : 0;
            uint32_t off = (uint32_t)(row * 256 + ((c ^ (row & 7)) << 4));
            CP16P(base + off, (const char*)(g_Xh + (size_t)gr * 128 + c * 8), valid);
        }
        CP_COMMIT;
    };

    if (y < totTiles) prefetchA(y, 0); else CP_COMMIT;

    int aR = (lane & 15);
    int aC = lane >> 4;
    int bR = (lane & 7) + ((lane >> 4) << 3);
    int bC = (lane >> 3) & 1;

    // ---- hoist ALL B fragments into registers (B is tile-invariant)
    CP_WAIT1;              // own B parts done (A0 may be pending)
    __syncthreads();       // all threads' B parts visible
    uint32_t bfr[8][2][4];
    #pragma unroll
    for (int ks = 0; ks < 8; ks++) {
        #pragma unroll
        for (int np = 0; np < 2; np++) {
            int row = wn * 32 + np * 16 + bR;
            int ch = ks * 2 + bC;
            uint32_t off = (uint32_t)(row * 256 + ((ch ^ (row & 7)) << 4));
            ldsm_x4(bfr[ks][np][0], bfr[ks][np][1], bfr[ks][np][2], bfr[ks][np][3],
                    sb + SM_B + off);
        }
    }

    int i = 0;
    for (int t = y; t < totTiles; t += NY, i++) {
        int tn = t + NY;
        if (tn < totTiles) prefetchA(tn, (i + 1) & 1); else CP_COMMIT;
        CP_WAIT1;
        __syncthreads();

        uint32_t aBase = sb + SM_A + (i & 1) * A_STAGE;

        float acc[2][4][4];
        #pragma unroll
        for (int mt = 0; mt < 2; mt++)
            #pragma unroll
            for (int nt = 0; nt < 4; nt++)
                #pragma unroll
                for (int q = 0; q < 4; q++) acc[mt][nt][q] = 0.f;

        #pragma unroll
        for (int ks = 0; ks < 8; ks++) {
            uint32_t a[2][4];
            #pragma unroll
            for (int mt = 0; mt < 2; mt++) {
                int row = wm * 32 + mt * 16 + aR;
                int ch = ks * 2 + aC;
                uint32_t off = (uint32_t)(row * 256 + ((ch ^ (row & 7)) << 4));
                ldsm_x4(a[mt][0], a[mt][1], a[mt][2], a[mt][3], aBase + off);
            }
            #pragma unroll
            for (int mt = 0; mt < 2; mt++)
                #pragma unroll
                for (int nt = 0; nt < 4; nt++) {
                    int hp = nt >> 1, qp = (nt & 1) * 2;
                    mma16816(acc[mt][nt], a[mt], bfr[ks][hp][qp], bfr[ks][hp][qp + 1]);
                }
        }

        int bm = t * BM;
        #pragma unroll
        for (int mt = 0; mt < 2; mt++) {
            #pragma unroll
            for (int h = 0; h < 2; h++) {
                int row = bm + wm * 32 + mt * 16 + (lane >> 2) + h * 8;
                if (row < M) {
                    __half* dst = g_table + (size_t)row * NCOLS + bn + wn * 32 + (lane & 3) * 2;
                    #pragma unroll
                    for (int nt = 0; nt < 4; nt++)
                        *(__half2*)(dst + nt * 8) =
                            __floats2half2_rn(acc[mt][nt][h * 2], acc[mt][nt][h * 2 + 1]);
                }
            }
        }
        __syncthreads();
    }
}

// ---------------------------------------------------------------------------
// Edge kernel: warp handles 2 edges (R6 shape, fp16 table).
// ---------------------------------------------------------------------------
__global__ __launch_bounds__(256) void edge_kernel(const void* __restrict__ idx,
                                                   const float* __restrict__ W2,
                                                   const float* __restrict__ b2,
                                                   float* __restrict__ out, int E) {
    int lane = threadIdx.x & 31;
    int e0 = blockIdx.x * 16 + (threadIdx.x >> 5) * 2;
    if (e0 >= E) return;
    bool has2 = (e0 + 1 < E);
    int o = lane * 8;

    int r0, c0, r1 = 0, c1 = 0;
    if (g_is64) {
        const long long* p = (const long long*)idx;
        r0 = (int)p[e0]; c0 = (int)p[E + e0];
        if (has2) { r1 = (int)p[e0 + 1]; c1 = (int)p[E + e0 + 1]; }
    } else {
        const int* p = (const int*)idx;
        r0 = p[e0]; c0 = p[E + e0];
        if (has2) { r1 = p[e0 + 1]; c1 = p[E + e0 + 1]; }
    }

    const __half* Tr0 = g_table + (size_t)r0 * NCOLS;
    const __half* Tc0 = g_table + (size_t)c0 * NCOLS;
    const __half* Tr1 = g_table + (size_t)(has2 ? r1 : r0) * NCOLS;
    const __half* Tc1 = g_table + (size_t)(has2 ? c1 : c0) * NCOLS;

    uint4 a0 = *(const uint4*)(Tr0 + o);          // seg0
    uint4 a2 = *(const uint4*)(Tr0 + 256 + o);    // seg2
    uint4 b1 = *(const uint4*)(Tc0 + 512 + o);    // seg1
    uint4 b3 = *(const uint4*)(Tc0 + 768 + o);    // seg3
    uint4 d0 = *(const uint4*)(Tr1 + o);
    uint4 d2 = *(const uint4*)(Tr1 + 256 + o);
    uint4 e1v = *(const uint4*)(Tc1 + 512 + o);
    uint4 e3 = *(const uint4*)(Tc1 + 768 + o);

    float cc[8], ww[8];
    *(float4*)(cc)     = *(const float4*)(g_c + o);
    *(float4*)(cc + 4) = *(const float4*)(g_c + o + 4);
    *(float4*)(ww)     = *(const float4*)(W2 + o);
    *(float4*)(ww + 4) = *(const float4*)(W2 + o + 4);

    const uint32_t* pa0 = &a0.x; const uint32_t* pa2 = &a2.x;
    const uint32_t* pb1 = &b1.x; const uint32_t* pb3 = &b3.x;
    const uint32_t* pd0 = &d0.x; const uint32_t* pd2 = &d2.x;
    const uint32_t* pe1 = &e1v.x; const uint32_t* pe3 = &e3.x;

    float accA = 0.f, accB = 0.f;
    #pragma unroll
    for (int j = 0; j < 4; j++) {
        float2 fa0 = __half22float2(*reinterpret_cast<const __half2*>(&pa0[j]));
        float2 fb1 = __half22float2(*reinterpret_cast<const __half2*>(&pb1[j]));
        float2 fa2 = __half22float2(*reinterpret_cast<const __half2*>(&pa2[j]));
        float2 fb3 = __half22float2(*reinterpret_cast<const __half2*>(&pb3[j]));
        float2 fd0 = __half22float2(*reinterpret_cast<const __half2*>(&pd0[j]));
        float2 fe1 = __half22float2(*reinterpret_cast<const __half2*>(&pe1[j]));
        float2 fd2 = __half22float2(*reinterpret_cast<const __half2*>(&pd2[j]));
        float2 fe3 = __half22float2(*reinterpret_cast<const __half2*>(&pe3[j]));
        float cx = cc[j * 2], cy = cc[j * 2 + 1];
        float wx = ww[j * 2], wy = ww[j * 2 + 1];
        accA += fmaxf(fa0.x + fb1.x + cx, 0.f) * wx;
        accA += fmaxf(fa0.y + fb1.y + cy, 0.f) * wy;
        accA += fmaxf(fa2.x + fb3.x + cx, 0.f) * wx;
        accA += fmaxf(fa2.y + fb3.y + cy, 0.f) * wy;
        accB += fmaxf(fd0.x + fe1.x + cx, 0.f) * wx;
        accB += fmaxf(fd0.y + fe1.y + cy, 0.f) * wy;
        accB += fmaxf(fd2.x + fe3.x + cx, 0.f) * wx;
        accB += fmaxf(fd2.y + fe3.y + cy, 0.f) * wy;
    }
    #pragma unroll
    for (int s = 16; s; s >>= 1) {
        accA += __shfl_xor_sync(0xFFFFFFFFu, accA, s);
        accB += __shfl_xor_sync(0xFFFFFFFFu, accB, s);
    }

    if (lane == 0) {
        float x = accA * 0.5f + b2[0];
        out[e0] = 1.f / (1.f + expf(-x));
        if (has2) {
            float x2 = accB * 0.5f + b2[0];
            out[e0 + 1] = 1.f / (1.f + expf(-x2));
        }
    }
}

// ---------------------------------------------------------------------------
extern "C" void kernel_launch(void* const* d_in, const int* in_sizes, int n_in,
                              void* d_out, int out_size) {
    const float* node_feat = (const float*)d_in[0];
    const void*  eidx      = d_in[1];
    const float* W1        = (const float*)d_in[2];
    const float* b1        = (const float*)d_in[3];
    const float* gamma     = (const float*)d_in[4];
    const float* beta      = (const float*)d_in[5];
    const float* mean      = (const float*)d_in[6];
    const float* var       = (const float*)d_in[7];
    const float* W2        = (const float*)d_in[8];
    const float* b2        = (const float*)d_in[9];
    float* out = (float*)d_out;

    int M = in_sizes[0] / NODE_DIM;   // 50000
    int E = out_size;                 // 300000

    cudaFuncSetAttribute(gemm_mma_kernel, cudaFuncAttributeMaxDynamicSharedMemorySize, SM_TOTAL);

    detect_kernel<<<1, 32>>>((const int*)eidx);
    prep_w_kernel<<<(NCOLS * NODE_DIM + 255) / 256, 256>>>(W1, b1, gamma, beta, mean, var);
    prep_x_kernel<<<(M * NODE_DIM / 4 + 255) / 256, 256>>>(node_feat, M * NODE_DIM / 4);

    dim3 ggrid(NCOLS / BN, 9);   // 144 persistent CTAs, 1/SM
    gemm_mma_kernel<<<ggrid, 256, SM_TOTAL>>>(M);

    edge_kernel<<<(E + 15) / 16, 256>>>(eidx, W2, b2, out, E);
}

// round 9
// speedup vs baseline: 1.4579x; 1.1460x over previous
#include <cuda_runtime.h>
#include <cuda_fp16.h>
#include <cstdint>

#define N_NODES_MAX 50000
#define NODE_DIM    128
#define HIDDEN      256
#define NCOLS       1024

// Table column layout (permuted for edge locality):
//   [0:256)=seg0 (p1 row)  [256:512)=seg2 (p2 row)
//   [512:768)=seg1 (p1 col) [768:1024)=seg3 (p2 col)

__device__ __half g_table[(size_t)N_NODES_MAX * NCOLS];   // 102.4 MB
__device__ __half g_Xh[(size_t)N_NODES_MAX * NODE_DIM];   // 12.8 MB
__device__ __half g_WTh[NCOLS * NODE_DIM];                // [n][k] permuted
__device__ float  g_c[HIDDEN];
__device__ int    g_is64;

__device__ __forceinline__ uint32_t smem_u32(const void* p) {
    uint32_t a;
    asm("{ .reg .u64 t; cvta.to.shared.u64 t, %1; cvt.u32.u64 %0, t; }" : "=r"(a) : "l"(p));
    return a;
}
__device__ __forceinline__ void ldsm_x4(uint32_t& r0, uint32_t& r1, uint32_t& r2, uint32_t& r3,
                                        uint32_t addr) {
    asm volatile("ldmatrix.sync.aligned.m8n8.x4.shared.b16 {%0,%1,%2,%3}, [%4];"
                 : "=r"(r0), "=r"(r1), "=r"(r2), "=r"(r3) : "r"(addr));
}
__device__ __forceinline__ void mma16816(float* c, const uint32_t* a, uint32_t b0, uint32_t b1) {
    asm volatile("mma.sync.aligned.m16n8k16.row.col.f32.f16.f16.f32 "
                 "{%0,%1,%2,%3}, {%4,%5,%6,%7}, {%8,%9}, {%0,%1,%2,%3};"
                 : "+f"(c[0]), "+f"(c[1]), "+f"(c[2]), "+f"(c[3])
                 : "r"(a[0]), "r"(a[1]), "r"(a[2]), "r"(a[3]), "r"(b0), "r"(b1));
}
#define CP16(dst, src) \
    asm volatile("cp.async.cg.shared.global [%0], [%1], 16;" :: "r"(dst), "l"(src))
#define CP16P(dst, src, p) \
    asm volatile("{ .reg .pred q; setp.ne.b32 q, %2, 0;\n\t" \
                 "@q cp.async.cg.shared.global [%0], [%1], 16; }" \
                 :: "r"(dst), "l"(src), "r"(p))
#define CP_COMMIT  asm volatile("cp.async.commit_group;")
#define CP_WAIT1   asm volatile("cp.async.wait_group 1;")

// ---------------------------------------------------------------------------
__global__ void detect_kernel(const int* __restrict__ idx32) {
    int lane = threadIdx.x;
    int acc = 0;
    for (int i = lane; i < 1024; i += 32) acc |= idx32[2 * i + 1];
    #pragma unroll
    for (int s = 16; s; s >>= 1) acc |= __shfl_xor_sync(0xFFFFFFFFu, acc, s);
    if (lane == 0) g_is64 = (acc == 0) ? 1 : 0;
}

// ---------------------------------------------------------------------------
__global__ void prep_w_kernel(const float* __restrict__ W1, const float* __restrict__ b1,
                              const float* __restrict__ gamma, const float* __restrict__ beta,
                              const float* __restrict__ mean, const float* __restrict__ var) {
    int i = blockIdx.x * blockDim.x + threadIdx.x;
    if (i < NCOLS * NODE_DIM) {
        int n = i >> 7;
        int k = i & 127;
        int h = n & 255;
        int grp = n >> 8;
        int srcRow;
        if (grp == 0)      srcRow = k;
        else if (grp == 1) srcRow = k + 16;
        else if (grp == 2) srcRow = 128 + k;
        else               srcRow = (k + 144) & 255;
        float s = gamma[h] * rsqrtf(var[h] + 1e-5f);
        g_WTh[i] = __float2half_rn(W1[srcRow * 256 + h] * s);
    }
    if (i < HIDDEN) {
        float s = gamma[i] * rsqrtf(var[i] + 1e-5f);
        g_c[i] = b1[i] * s + beta[i] - mean[i] * s;
    }
}

__global__ void prep_x_kernel(const float* __restrict__ X, int total4) {
    int i = blockIdx.x * blockDim.x + threadIdx.x;
    if (i >= total4) return;
    float4 v = *(const float4*)(X + i * 4);
    __half2* dst = (__half2*)(g_Xh + i * 4);
    dst[0] = __floats2half2_rn(v.x, v.y);
    dst[1] = __floats2half2_rn(v.z, v.w);
}

// ---------------------------------------------------------------------------
// Persistent warp-MMA fp16 GEMM. BM=128, BN=128 (8 bn groups), warp 32x64.
// A double-buffered; writeback staged through smem for 16B coalesced stores.
// smem: B 32KB + 2 x 32KB A stages = 96KB -> 2 CTAs/SM.
// ---------------------------------------------------------------------------
#define BM 128
#define BN 128
#define SM_B    0
#define SM_A    32768
#define A_STAGE 32768
#define SM_TOTAL 98304
#define STG_STRIDE 272   // bytes per staged row (16B pad -> conflict-free)

__global__ __launch_bounds__(256, 2) void gemm_mma_kernel(int M) {
    extern __shared__ char smem[];
    uint32_t sb = smem_u32(smem);
    int tid = threadIdx.x;
    int lane = tid & 31;
    int wid = tid >> 5;
    int wm = wid & 3;     // 4 warps over M (32 rows each)
    int wn = wid >> 2;    // 2 warps over N (64 cols each)
    int bn = blockIdx.x * BN;
    int y = blockIdx.y;
    int NY = gridDim.y;
    int totTiles = (M + BM - 1) / BM;

    // B tile (128 n-rows x 128 k) swizzled (group 0)
    for (int s = tid; s < 2048; s += 256) {
        int row = s >> 4;
        int c = s & 15;
        uint32_t off = (uint32_t)(row * 256 + ((c ^ (row & 7)) << 4));
        CP16(sb + SM_B + off, (const char*)(g_WTh + (size_t)(bn + row) * 128 + c * 8));
    }
    CP_COMMIT;

    auto prefetchA = [&](int t, int st) {
        int bm = t * BM;
        uint32_t base = sb + SM_A + st * A_STAGE;
        for (int s = tid; s < 2048; s += 256) {
            int row = s >> 4;
            int c = s & 15;
            int gr = bm + row;
            int valid = (gr < M) ? 1 : 0;
            uint32_t off = (uint32_t)(row * 256 + ((c ^ (row & 7)) << 4));
            CP16P(base + off, (const char*)(g_Xh + (size_t)gr * 128 + c * 8), valid);
        }
        CP_COMMIT;
    };

    if (y < totTiles) prefetchA(y, 0); else CP_COMMIT;

    int aR = (lane & 15);
    int aC = lane >> 4;
    int bR = (lane & 7) + ((lane >> 4) << 3);
    int bC = (lane >> 3) & 1;

    int i = 0;
    for (int t = y; t < totTiles; t += NY, i++) {
        int tn = t + NY;
        if (tn < totTiles) prefetchA(tn, (i + 1) & 1); else CP_COMMIT;
        CP_WAIT1;
        __syncthreads();

        uint32_t aBase = sb + SM_A + (i & 1) * A_STAGE;

        float acc[2][8][4];
        #pragma unroll
        for (int mt = 0; mt < 2; mt++)
            #pragma unroll
            for (int nt = 0; nt < 8; nt++)
                #pragma unroll
                for (int q = 0; q < 4; q++) acc[mt][nt][q] = 0.f;

        #pragma unroll
        for (int ks = 0; ks < 8; ks++) {
            uint32_t a[2][4], b[4][4];
            #pragma unroll
            for (int mt = 0; mt < 2; mt++) {
                int row = wm * 32 + mt * 16 + aR;
                int ch = ks * 2 + aC;
                uint32_t off = (uint32_t)(row * 256 + ((ch ^ (row & 7)) << 4));
                ldsm_x4(a[mt][0], a[mt][1], a[mt][2], a[mt][3], aBase + off);
            }
            #pragma unroll
            for (int np = 0; np < 4; np++) {
                int row = wn * 64 + np * 16 + bR;
                int ch = ks * 2 + bC;
                uint32_t off = (uint32_t)(row * 256 + ((ch ^ (row & 7)) << 4));
                ldsm_x4(b[np][0], b[np][1], b[np][2], b[np][3], sb + SM_B + off);
            }
            #pragma unroll
            for (int mt = 0; mt < 2; mt++)
                #pragma unroll
                for (int nt = 0; nt < 8; nt++) {
                    int np = nt >> 1, qp = (nt & 1) * 2;
                    mma16816(acc[mt][nt], a[mt], b[np][qp], b[np][qp + 1]);
                }
        }

        // ---- staged writeback: 2 passes of 64 rows each through the free stage
        int bm = t * BM;
        char* stg = smem + SM_A + (i & 1) * A_STAGE;   // just-consumed stage
        #pragma unroll
        for (int p = 0; p < 2; p++) {
            __syncthreads();
            if ((wm >> 1) == p) {
                int lrb = (wm & 1) * 32;
                #pragma unroll
                for (int mt = 0; mt < 2; mt++)
                    #pragma unroll
                    for (int h = 0; h < 2; h++) {
                        int lr = lrb + mt * 16 + (lane >> 2) + h * 8;
                        char* rowp = stg + lr * STG_STRIDE + wn * 128 + (lane & 3) * 4;
                        #pragma unroll
                        for (int nt = 0; nt < 8; nt++)
                            *(__half2*)(rowp + nt * 16) =
                                __floats2half2_rn(acc[mt][nt][h * 2], acc[mt][nt][h * 2 + 1]);
                    }
            }
            __syncthreads();
            // coalesced global: 64 rows x 256B
            for (int s = tid; s < 1024; s += 256) {
                int lr = s >> 4;
                int c = s & 15;
                int gr = bm + p * 64 + lr;
                if (gr < M)
                    *(uint4*)(g_table + (size_t)gr * NCOLS + bn + c * 8) =
                        *(const uint4*)(stg + lr * STG_STRIDE + c * 16);
            }
        }
        __syncthreads();
    }
}

// ---------------------------------------------------------------------------
// Edge kernel: warp handles 2 edges (fp16 table).
// ---------------------------------------------------------------------------
__global__ __launch_bounds__(256) void edge_kernel(const void* __restrict__ idx,
                                                   const float* __restrict__ W2,
                                                   const float* __restrict__ b2,
                                                   float* __restrict__ out, int E) {
    int lane = threadIdx.x & 31;
    int e0 = blockIdx.x * 16 + (threadIdx.x >> 5) * 2;
    if (e0 >= E) return;
    bool has2 = (e0 + 1 < E);
    int o = lane * 8;

    int r0, c0, r1 = 0, c1 = 0;
    if (g_is64) {
        const long long* p = (const long long*)idx;
        r0 = (int)p[e0]; c0 = (int)p[E + e0];
        if (has2) { r1 = (int)p[e0 + 1]; c1 = (int)p[E + e0 + 1]; }
    } else {
        const int* p = (const int*)idx;
        r0 = p[e0]; c0 = p[E + e0];
        if (has2) { r1 = p[e0 + 1]; c1 = p[E + e0 + 1]; }
    }

    const __half* Tr0 = g_table + (size_t)r0 * NCOLS;
    const __half* Tc0 = g_table + (size_t)c0 * NCOLS;
    const __half* Tr1 = g_table + (size_t)(has2 ? r1 : r0) * NCOLS;
    const __half* Tc1 = g_table + (size_t)(has2 ? c1 : c0) * NCOLS;

    uint4 a0 = *(const uint4*)(Tr0 + o);
    uint4 a2 = *(const uint4*)(Tr0 + 256 + o);
    uint4 b1 = *(const uint4*)(Tc0 + 512 + o);
    uint4 b3 = *(const uint4*)(Tc0 + 768 + o);
    uint4 d0 = *(const uint4*)(Tr1 + o);
    uint4 d2 = *(const uint4*)(Tr1 + 256 + o);
    uint4 e1v = *(const uint4*)(Tc1 + 512 + o);
    uint4 e3 = *(const uint4*)(Tc1 + 768 + o);

    float cc[8], ww[8];
    *(float4*)(cc)     = *(const float4*)(g_c + o);
    *(float4*)(cc + 4) = *(const float4*)(g_c + o + 4);
    *(float4*)(ww)     = *(const float4*)(W2 + o);
    *(float4*)(ww + 4) = *(const float4*)(W2 + o + 4);

    const uint32_t* pa0 = &a0.x; const uint32_t* pa2 = &a2.x;
    const uint32_t* pb1 = &b1.x; const uint32_t* pb3 = &b3.x;
    const uint32_t* pd0 = &d0.x; const uint32_t* pd2 = &d2.x;
    const uint32_t* pe1 = &e1v.x; const uint32_t* pe3 = &e3.x;

    float accA = 0.f, accB = 0.f;
    #pragma unroll
    for (int j = 0; j < 4; j++) {
        float2 fa0 = __half22float2(*reinterpret_cast<const __half2*>(&pa0[j]));
        float2 fb1 = __half22float2(*reinterpret_cast<const __half2*>(&pb1[j]));
        float2 fa2 = __half22float2(*reinterpret_cast<const __half2*>(&pa2[j]));
        float2 fb3 = __half22float2(*reinterpret_cast<const __half2*>(&pb3[j]));
        float2 fd0 = __half22float2(*reinterpret_cast<const __half2*>(&pd0[j]));
        float2 fe1 = __half22float2(*reinterpret_cast<const __half2*>(&pe1[j]));
        float2 fd2 = __half22float2(*reinterpret_cast<const __half2*>(&pd2[j]));
        float2 fe3 = __half22float2(*reinterpret_cast<const __half2*>(&pe3[j]));
        float cx = cc[j * 2], cy = cc[j * 2 + 1];
        float wx = ww[j * 2], wy = ww[j * 2 + 1];
        accA += fmaxf(fa0.x + fb1.x + cx, 0.f) * wx;
        accA += fmaxf(fa0.y + fb1.y + cy, 0.f) * wy;
        accA += fmaxf(fa2.x + fb3.x + cx, 0.f) * wx;
        accA += fmaxf(fa2.y + fb3.y + cy, 0.f) * wy;
        accB += fmaxf(fd0.x + fe1.x + cx, 0.f) * wx;
        accB += fmaxf(fd0.y + fe1.y + cy, 0.f) * wy;
        accB += fmaxf(fd2.x + fe3.x + cx, 0.f) * wx;
        accB += fmaxf(fd2.y + fe3.y + cy, 0.f) * wy;
    }
    #pragma unroll
    for (int s = 16; s; s >>= 1) {
        accA += __shfl_xor_sync(0xFFFFFFFFu, accA, s);
        accB += __shfl_xor_sync(0xFFFFFFFFu, accB, s);
    }

    if (lane == 0) {
        float x = accA * 0.5f + b2[0];
        out[e0] = 1.f / (1.f + expf(-x));
        if (has2) {
            float x2 = accB * 0.5f + b2[0];
            out[e0 + 1] = 1.f / (1.f + expf(-x2));
        }
    }
}

// ---------------------------------------------------------------------------
extern "C" void kernel_launch(void* const* d_in, const int* in_sizes, int n_in,
                              void* d_out, int out_size) {
    const float* node_feat = (const float*)d_in[0];
    const void*  eidx      = d_in[1];
    const float* W1        = (const float*)d_in[2];
    const float* b1        = (const float*)d_in[3];
    const float* gamma     = (const float*)d_in[4];
    const float* beta      = (const float*)d_in[5];
    const float* mean      = (const float*)d_in[6];
    const float* var       = (const float*)d_in[7];
    const float* W2        = (const float*)d_in[8];
    const float* b2        = (const float*)d_in[9];
    float* out = (float*)d_out;

    int M = in_sizes[0] / NODE_DIM;   // 50000
    int E = out_size;                 // 300000

    cudaFuncSetAttribute(gemm_mma_kernel, cudaFuncAttributeMaxDynamicSharedMemorySize, SM_TOTAL);

    detect_kernel<<<1, 32>>>((const int*)eidx);
    prep_w_kernel<<<(NCOLS * NODE_DIM + 255) / 256, 256>>>(W1, b1, gamma, beta, mean, var);
    prep_x_kernel<<<(M * NODE_DIM / 4 + 255) / 256, 256>>>(node_feat, M * NODE_DIM / 4);

    dim3 ggrid(NCOLS / BN, 36);   // (8, 36) = 288 persistent CTAs, 2/SM
    gemm_mma_kernel<<<ggrid, 256, SM_TOTAL>>>(M);

    edge_kernel<<<(E + 15) / 16, 256>>>(eidx, W2, b2, out, E);
}

// round 10
// speedup vs baseline: 1.4892x; 1.0214x over previous
#include <cuda_runtime.h>
#include <cuda_fp16.h>
#include <cstdint>

#define N_NODES_MAX 50000
#define N_EDGES_MAX 524288
#define NODE_DIM    128
#define HIDDEN      256
#define NCOLS       1024

// Table column layout: [0:256)=seg0 (p1 row), [256:512)=seg2 (p2 row),
//                      [512:768)=seg1 (p1 col), [768:1024)=seg3 (p2 col)

__device__ __half g_table[(size_t)N_NODES_MAX * NCOLS];   // 102.4 MB
__device__ __half g_Xh[(size_t)N_NODES_MAX * NODE_DIM];   // 12.8 MB
__device__ __half g_WTh[NCOLS * NODE_DIM];                // [n][k] permuted
__device__ float  g_c[HIDDEN];
__device__ float  g_partial[N_EDGES_MAX];                 // p1 scratch
__device__ int    g_is64;

__device__ __forceinline__ uint32_t smem_u32(const void* p) {
    uint32_t a;
    asm("{ .reg .u64 t; cvta.to.shared.u64 t, %1; cvt.u32.u64 %0, t; }" : "=r"(a) : "l"(p));
    return a;
}
__device__ __forceinline__ void ldsm_x4(uint32_t& r0, uint32_t& r1, uint32_t& r2, uint32_t& r3,
                                        uint32_t addr) {
    asm volatile("ldmatrix.sync.aligned.m8n8.x4.shared.b16 {%0,%1,%2,%3}, [%4];"
                 : "=r"(r0), "=r"(r1), "=r"(r2), "=r"(r3) : "r"(addr));
}
__device__ __forceinline__ void mma16816(float* c, const uint32_t* a, uint32_t b0, uint32_t b1) {
    asm volatile("mma.sync.aligned.m16n8k16.row.col.f32.f16.f16.f32 "
                 "{%0,%1,%2,%3}, {%4,%5,%6,%7}, {%8,%9}, {%0,%1,%2,%3};"
                 : "+f"(c[0]), "+f"(c[1]), "+f"(c[2]), "+f"(c[3])
                 : "r"(a[0]), "r"(a[1]), "r"(a[2]), "r"(a[3]), "r"(b0), "r"(b1));
}
#define CP16(dst, src) \
    asm volatile("cp.async.cg.shared.global [%0], [%1], 16;" :: "r"(dst), "l"(src))
#define CP16P(dst, src, p) \
    asm volatile("{ .reg .pred q; setp.ne.b32 q, %2, 0;\n\t" \
                 "@q cp.async.cg.shared.global [%0], [%1], 16; }" \
                 :: "r"(dst), "l"(src), "r"(p))
#define CP_COMMIT  asm volatile("cp.async.commit_group;")
#define CP_WAIT1   asm volatile("cp.async.wait_group 1;")

// ---------------------------------------------------------------------------
// Fused prep: blocks [0,512) -> W fold; [512,512+nx) -> X fp16; last -> c + detect
// ---------------------------------------------------------------------------
__global__ void prep_all_kernel(const float* __restrict__ X,
                                const float* __restrict__ W1, const float* __restrict__ b1,
                                const float* __restrict__ gamma, const float* __restrict__ beta,
                                const float* __restrict__ mean, const float* __restrict__ var,
                                const int* __restrict__ idx32, int nx, int total4) {
    int b = blockIdx.x;
    int tid = threadIdx.x;
    if (b < 512) {
        int i = b * 256 + tid;   // i < 131072 always
        int n = i >> 7;
        int k = i & 127;
        int h = n & 255;
        int grp = n >> 8;
        int srcRow;
        if (grp == 0)      srcRow = k;
        else if (grp == 1) srcRow = k + 16;
        else if (grp == 2) srcRow = 128 + k;
        else               srcRow = (k + 144) & 255;
        float s = gamma[h] * rsqrtf(var[h] + 1e-5f);
        g_WTh[i] = __float2half_rn(W1[srcRow * 256 + h] * s);
    } else if (b < 512 + nx) {
        int i = (b - 512) * 256 + tid;
        if (i < total4) {
            float4 v = *(const float4*)(X + i * 4);
            __half2* dst = (__half2*)(g_Xh + i * 4);
            dst[0] = __floats2half2_rn(v.x, v.y);
            dst[1] = __floats2half2_rn(v.z, v.w);
        }
    } else {
        if (tid < HIDDEN) {
            float s = gamma[tid] * rsqrtf(var[tid] + 1e-5f);
            g_c[tid] = b1[tid] * s + beta[tid] - mean[tid] * s;
        }
        if (tid < 32) {
            int acc = 0;
            for (int i = tid; i < 1024; i += 32) acc |= idx32[2 * i + 1];
            #pragma unroll
            for (int s = 16; s; s >>= 1) acc |= __shfl_xor_sync(0xFFFFFFFFu, acc, s);
            if (tid == 0) g_is64 = (acc == 0) ? 1 : 0;
        }
    }
}

// ---------------------------------------------------------------------------
// Persistent warp-MMA fp16 GEMM (unchanged R9 winner).
// ---------------------------------------------------------------------------
#define BM 128
#define BN 128
#define SM_B    0
#define SM_A    32768
#define A_STAGE 32768
#define SM_TOTAL 98304
#define STG_STRIDE 272

__global__ __launch_bounds__(256, 2) void gemm_mma_kernel(int M) {
    extern __shared__ char smem[];
    uint32_t sb = smem_u32(smem);
    int tid = threadIdx.x;
    int lane = tid & 31;
    int wid = tid >> 5;
    int wm = wid & 3;
    int wn = wid >> 2;
    int bn = blockIdx.x * BN;
    int y = blockIdx.y;
    int NY = gridDim.y;
    int totTiles = (M + BM - 1) / BM;

    for (int s = tid; s < 2048; s += 256) {
        int row = s >> 4;
        int c = s & 15;
        uint32_t off = (uint32_t)(row * 256 + ((c ^ (row & 7)) << 4));
        CP16(sb + SM_B + off, (const char*)(g_WTh + (size_t)(bn + row) * 128 + c * 8));
    }
    CP_COMMIT;

    auto prefetchA = [&](int t, int st) {
        int bm = t * BM;
        uint32_t base = sb + SM_A + st * A_STAGE;
        for (int s = tid; s < 2048; s += 256) {
            int row = s >> 4;
            int c = s & 15;
            int gr = bm + row;
            int valid = (gr < M) ? 1 : 0;
            uint32_t off = (uint32_t)(row * 256 + ((c ^ (row & 7)) << 4));
            CP16P(base + off, (const char*)(g_Xh + (size_t)gr * 128 + c * 8), valid);
        }
        CP_COMMIT;
    };

    if (y < totTiles) prefetchA(y, 0); else CP_COMMIT;

    int aR = (lane & 15);
    int aC = lane >> 4;
    int bR = (lane & 7) + ((lane >> 4) << 3);
    int bC = (lane >> 3) & 1;

    int i = 0;
    for (int t = y; t < totTiles; t += NY, i++) {
        int tn = t + NY;
        if (tn < totTiles) prefetchA(tn, (i + 1) & 1); else CP_COMMIT;
        CP_WAIT1;
        __syncthreads();

        uint32_t aBase = sb + SM_A + (i & 1) * A_STAGE;

        float acc[2][8][4];
        #pragma unroll
        for (int mt = 0; mt < 2; mt++)
            #pragma unroll
            for (int nt = 0; nt < 8; nt++)
                #pragma unroll
                for (int q = 0; q < 4; q++) acc[mt][nt][q] = 0.f;

        #pragma unroll
        for (int ks = 0; ks < 8; ks++) {
            uint32_t a[2][4], b[4][4];
            #pragma unroll
            for (int mt = 0; mt < 2; mt++) {
                int row = wm * 32 + mt * 16 + aR;
                int ch = ks * 2 + aC;
                uint32_t off = (uint32_t)(row * 256 + ((ch ^ (row & 7)) << 4));
                ldsm_x4(a[mt][0], a[mt][1], a[mt][2], a[mt][3], aBase + off);
            }
            #pragma unroll
            for (int np = 0; np < 4; np++) {
                int row = wn * 64 + np * 16 + bR;
                int ch = ks * 2 + bC;
                uint32_t off = (uint32_t)(row * 256 + ((ch ^ (row & 7)) << 4));
                ldsm_x4(b[np][0], b[np][1], b[np][2], b[np][3], sb + SM_B + off);
            }
            #pragma unroll
            for (int mt = 0; mt < 2; mt++)
                #pragma unroll
                for (int nt = 0; nt < 8; nt++) {
                    int np = nt >> 1, qp = (nt & 1) * 2;
                    mma16816(acc[mt][nt], a[mt], b[np][qp], b[np][qp + 1]);
                }
        }

        int bm = t * BM;
        char* stg = smem + SM_A + (i & 1) * A_STAGE;
        #pragma unroll
        for (int p = 0; p < 2; p++) {
            __syncthreads();
            if ((wm >> 1) == p) {
                int lrb = (wm & 1) * 32;
                #pragma unroll
                for (int mt = 0; mt < 2; mt++)
                    #pragma unroll
                    for (int h = 0; h < 2; h++) {
                        int lr = lrb + mt * 16 + (lane >> 2) + h * 8;
                        char* rowp = stg + lr * STG_STRIDE + wn * 128 + (lane & 3) * 4;
                        #pragma unroll
                        for (int nt = 0; nt < 8; nt++)
                            *(__half2*)(rowp + nt * 16) =
                                __floats2half2_rn(acc[mt][nt][h * 2], acc[mt][nt][h * 2 + 1]);
                    }
            }
            __syncthreads();
            for (int s = tid; s < 1024; s += 256) {
                int lr = s >> 4;
                int c = s & 15;
                int gr = bm + p * 64 + lr;
                if (gr < M)
                    *(uint4*)(g_table + (size_t)gr * NCOLS + bn + c * 8) =
                        *(const uint4*)(stg + lr * STG_STRIDE + c * 16);
            }
        }
        __syncthreads();
    }
}

// ---------------------------------------------------------------------------
// Edge passes: each pass touches a disjoint 51MB working set (fits L2 well).
// 4 edges/warp, 8 streams of 512B.
//   PASS=0: acc = relu-dot over (Tr+0, Tc+512), store g_partial
//   PASS=1: acc over (Tr+256, Tc+768); out = sigmoid((p1+acc)*0.5 + b2)
// ---------------------------------------------------------------------------
template <int PASS>
__global__ __launch_bounds__(256) void edge_pass_kernel(const void* __restrict__ idx,
                                                        const float* __restrict__ W2,
                                                        const float* __restrict__ b2,
                                                        float* __restrict__ out, int E) {
    int lane = threadIdx.x & 31;
    int e0 = blockIdx.x * 32 + (threadIdx.x >> 5) * 4;
    if (e0 >= E) return;
    int o = lane * 8;
    const int RO = PASS ? 256 : 0;
    const int CO = PASS ? 768 : 512;

    int r[4], c[4];
    if (g_is64) {
        const long long* p = (const long long*)idx;
        #pragma unroll
        for (int q = 0; q < 4; q++) {
            int e = min(e0 + q, E - 1);
            r[q] = (int)p[e]; c[q] = (int)p[E + e];
        }
    } else {
        const int* p = (const int*)idx;
        #pragma unroll
        for (int q = 0; q < 4; q++) {
            int e = min(e0 + q, E - 1);
            r[q] = p[e]; c[q] = p[E + e];
        }
    }

    uint4 rv[4], cv[4];
    #pragma unroll
    for (int q = 0; q < 4; q++) {
        rv[q] = *(const uint4*)(g_table + (size_t)r[q] * NCOLS + RO + o);
        cv[q] = *(const uint4*)(g_table + (size_t)c[q] * NCOLS + CO + o);
    }

    float cc[8], ww[8];
    *(float4*)(cc)     = *(const float4*)(g_c + o);
    *(float4*)(cc + 4) = *(const float4*)(g_c + o + 4);
    *(float4*)(ww)     = *(const float4*)(W2 + o);
    *(float4*)(ww + 4) = *(const float4*)(W2 + o + 4);

    float acc[4] = {0.f, 0.f, 0.f, 0.f};
    #pragma unroll
    for (int q = 0; q < 4; q++) {
        const uint32_t* pr = &rv[q].x;
        const uint32_t* pc = &cv[q].x;
        #pragma unroll
        for (int j = 0; j < 4; j++) {
            float2 fr = __half22float2(*reinterpret_cast<const __half2*>(&pr[j]));
            float2 fc = __half22float2(*reinterpret_cast<const __half2*>(&pc[j]));
            acc[q] += fmaxf(fr.x + fc.x + cc[j * 2], 0.f) * ww[j * 2];
            acc[q] += fmaxf(fr.y + fc.y + cc[j * 2 + 1], 0.f) * ww[j * 2 + 1];
        }
    }
    #pragma unroll
    for (int s = 16; s; s >>= 1) {
        #pragma unroll
        for (int q = 0; q < 4; q++)
            acc[q] += __shfl_xor_sync(0xFFFFFFFFu, acc[q], s);
    }

    if (lane < 4) {
        int e = e0 + lane;
        float v = __shfl_sync(0xFFFFFFFFu, acc[0], 0);   // placeholder; replaced below
        // gather this lane's acc: lane q holds acc[q] broadcast — select via shfl idx
        v = (lane == 0) ? acc[0] : (lane == 1) ? acc[1] : (lane == 2) ? acc[2] : acc[3];
        if (e < E) {
            if (PASS == 0) {
                g_partial[e] = v;
            } else {
                float x = (g_partial[e] + v) * 0.5f + b2[0];
                out[e] = 1.f / (1.f + expf(-x));
            }
        }
    }
}

// ---------------------------------------------------------------------------
extern "C" void kernel_launch(void* const* d_in, const int* in_sizes, int n_in,
                              void* d_out, int out_size) {
    const float* node_feat = (const float*)d_in[0];
    const void*  eidx      = d_in[1];
    const float* W1        = (const float*)d_in[2];
    const float* b1        = (const float*)d_in[3];
    const float* gamma     = (const float*)d_in[4];
    const float* beta      = (const float*)d_in[5];
    const float* mean      = (const float*)d_in[6];
    const float* var       = (const float*)d_in[7];
    const float* W2        = (const float*)d_in[8];
    const float* b2        = (const float*)d_in[9];
    float* out = (float*)d_out;

    int M = in_sizes[0] / NODE_DIM;   // 50000
    int E = out_size;                 // 300000

    cudaFuncSetAttribute(gemm_mma_kernel, cudaFuncAttributeMaxDynamicSharedMemorySize, SM_TOTAL);

    int total4 = M * NODE_DIM / 4;
    int nx = (total4 + 255) / 256;
    prep_all_kernel<<<512 + nx + 1, 256>>>(node_feat, W1, b1, gamma, beta, mean, var,
                                           (const int*)eidx, nx, total4);

    dim3 ggrid(NCOLS / BN, 36);   // 288 persistent CTAs, 2/SM
    gemm_mma_kernel<<<ggrid, 256, SM_TOTAL>>>(M);

    edge_pass_kernel<0><<<(E + 31) / 32, 256>>>(eidx, W2, b2, out, E);
    edge_pass_kernel<1><<<(E + 31) / 32, 256>>>(eidx, W2, b2, out, E);
}

// round 11
// speedup vs baseline: 1.9560x; 1.3135x over previous
#include <cuda_runtime.h>
#include <cuda_fp16.h>
#include <cstdint>

#define N_NODES_MAX 50000
#define NODE_DIM    128
#define HIDDEN      256
#define NCOLS       1024

// Table column layout: [0:256)=seg0 (p1 row), [256:512)=seg2 (p2 row),
//                      [512:768)=seg1 (p1 col), [768:1024)=seg3 (p2 col)
// => each edge reads Tr[0:512) and Tc[512:1024), both 1KB contiguous.

__device__ __half g_table[(size_t)N_NODES_MAX * NCOLS];   // 102.4 MB
__device__ __half g_Xh[(size_t)N_NODES_MAX * NODE_DIM];   // 12.8 MB
__device__ __half g_WTh[NCOLS * NODE_DIM];                // [n][k] permuted
__device__ __half g_ch[HIDDEN];                           // bias const, half
__device__ __half g_w2h[HIDDEN];                          // W2, half
__device__ int    g_is64;

__device__ __forceinline__ uint32_t smem_u32(const void* p) {
    uint32_t a;
    asm("{ .reg .u64 t; cvta.to.shared.u64 t, %1; cvt.u32.u64 %0, t; }" : "=r"(a) : "l"(p));
    return a;
}
__device__ __forceinline__ void ldsm_x4(uint32_t& r0, uint32_t& r1, uint32_t& r2, uint32_t& r3,
                                        uint32_t addr) {
    asm volatile("ldmatrix.sync.aligned.m8n8.x4.shared.b16 {%0,%1,%2,%3}, [%4];"
                 : "=r"(r0), "=r"(r1), "=r"(r2), "=r"(r3) : "r"(addr));
}
__device__ __forceinline__ void mma16816(float* c, const uint32_t* a, uint32_t b0, uint32_t b1) {
    asm volatile("mma.sync.aligned.m16n8k16.row.col.f32.f16.f16.f32 "
                 "{%0,%1,%2,%3}, {%4,%5,%6,%7}, {%8,%9}, {%0,%1,%2,%3};"
                 : "+f"(c[0]), "+f"(c[1]), "+f"(c[2]), "+f"(c[3])
                 : "r"(a[0]), "r"(a[1]), "r"(a[2]), "r"(a[3]), "r"(b0), "r"(b1));
}
#define CP16(dst, src) \
    asm volatile("cp.async.cg.shared.global [%0], [%1], 16;" :: "r"(dst), "l"(src))
#define CP16P(dst, src, p) \
    asm volatile("{ .reg .pred q; setp.ne.b32 q, %2, 0;\n\t" \
                 "@q cp.async.cg.shared.global [%0], [%1], 16; }" \
                 :: "r"(dst), "l"(src), "r"(p))
#define CP_COMMIT  asm volatile("cp.async.commit_group;")
#define CP_WAIT1   asm volatile("cp.async.wait_group 1;")

// ---------------------------------------------------------------------------
// Fused prep
// ---------------------------------------------------------------------------
__global__ void prep_all_kernel(const float* __restrict__ X,
                                const float* __restrict__ W1, const float* __restrict__ b1,
                                const float* __restrict__ gamma, const float* __restrict__ beta,
                                const float* __restrict__ mean, const float* __restrict__ var,
                                const float* __restrict__ W2,
                                const int* __restrict__ idx32, int nx, int total4) {
    int b = blockIdx.x;
    int tid = threadIdx.x;
    if (b < 512) {
        int i = b * 256 + tid;
        int n = i >> 7;
        int k = i & 127;
        int h = n & 255;
        int grp = n >> 8;
        int srcRow;
        if (grp == 0)      srcRow = k;
        else if (grp == 1) srcRow = k + 16;
        else if (grp == 2) srcRow = 128 + k;
        else               srcRow = (k + 144) & 255;
        float s = gamma[h] * rsqrtf(var[h] + 1e-5f);
        g_WTh[i] = __float2half_rn(W1[srcRow * 256 + h] * s);
    } else if (b < 512 + nx) {
        int i = (b - 512) * 256 + tid;
        if (i < total4) {
            float4 v = *(const float4*)(X + i * 4);
            __half2* dst = (__half2*)(g_Xh + i * 4);
            dst[0] = __floats2half2_rn(v.x, v.y);
            dst[1] = __floats2half2_rn(v.z, v.w);
        }
    } else {
        if (tid < HIDDEN) {
            float s = gamma[tid] * rsqrtf(var[tid] + 1e-5f);
            g_ch[tid] = __float2half_rn(b1[tid] * s + beta[tid] - mean[tid] * s);
            g_w2h[tid] = __float2half_rn(W2[tid]);
        }
        if (tid < 32) {
            int acc = 0;
            for (int i = tid; i < 1024; i += 32) acc |= idx32[2 * i + 1];
            #pragma unroll
            for (int s = 16; s; s >>= 1) acc |= __shfl_xor_sync(0xFFFFFFFFu, acc, s);
            if (tid == 0) g_is64 = (acc == 0) ? 1 : 0;
        }
    }
}

// ---------------------------------------------------------------------------
// Persistent warp-MMA fp16 GEMM (R9 winner, unchanged).
// ---------------------------------------------------------------------------
#define BM 128
#define BN 128
#define SM_B    0
#define SM_A    32768
#define A_STAGE 32768
#define SM_TOTAL 98304
#define STG_STRIDE 272

__global__ __launch_bounds__(256, 2) void gemm_mma_kernel(int M) {
    extern __shared__ char smem[];
    uint32_t sb = smem_u32(smem);
    int tid = threadIdx.x;
    int lane = tid & 31;
    int wid = tid >> 5;
    int wm = wid & 3;
    int wn = wid >> 2;
    int bn = blockIdx.x * BN;
    int y = blockIdx.y;
    int NY = gridDim.y;
    int totTiles = (M + BM - 1) / BM;

    for (int s = tid; s < 2048; s += 256) {
        int row = s >> 4;
        int c = s & 15;
        uint32_t off = (uint32_t)(row * 256 + ((c ^ (row & 7)) << 4));
        CP16(sb + SM_B + off, (const char*)(g_WTh + (size_t)(bn + row) * 128 + c * 8));
    }
    CP_COMMIT;

    auto prefetchA = [&](int t, int st) {
        int bm = t * BM;
        uint32_t base = sb + SM_A + st * A_STAGE;
        for (int s = tid; s < 2048; s += 256) {
            int row = s >> 4;
            int c = s & 15;
            int gr = bm + row;
            int valid = (gr < M) ? 1 : 0;
            uint32_t off = (uint32_t)(row * 256 + ((c ^ (row & 7)) << 4));
            CP16P(base + off, (const char*)(g_Xh + (size_t)gr * 128 + c * 8), valid);
        }
        CP_COMMIT;
    };

    if (y < totTiles) prefetchA(y, 0); else CP_COMMIT;

    int aR = (lane & 15);
    int aC = lane >> 4;
    int bR = (lane & 7) + ((lane >> 4) << 3);
    int bC = (lane >> 3) & 1;

    int i = 0;
    for (int t = y; t < totTiles; t += NY, i++) {
        int tn = t + NY;
        if (tn < totTiles) prefetchA(tn, (i + 1) & 1); else CP_COMMIT;
        CP_WAIT1;
        __syncthreads();

        uint32_t aBase = sb + SM_A + (i & 1) * A_STAGE;

        float acc[2][8][4];
        #pragma unroll
        for (int mt = 0; mt < 2; mt++)
            #pragma unroll
            for (int nt = 0; nt < 8; nt++)
                #pragma unroll
                for (int q = 0; q < 4; q++) acc[mt][nt][q] = 0.f;

        #pragma unroll
        for (int ks = 0; ks < 8; ks++) {
            uint32_t a[2][4], b[4][4];
            #pragma unroll
            for (int mt = 0; mt < 2; mt++) {
                int row = wm * 32 + mt * 16 + aR;
                int ch = ks * 2 + aC;
                uint32_t off = (uint32_t)(row * 256 + ((ch ^ (row & 7)) << 4));
                ldsm_x4(a[mt][0], a[mt][1], a[mt][2], a[mt][3], aBase + off);
            }
            #pragma unroll
            for (int np = 0; np < 4; np++) {
                int row = wn * 64 + np * 16 + bR;
                int ch = ks * 2 + bC;
                uint32_t off = (uint32_t)(row * 256 + ((ch ^ (row & 7)) << 4));
                ldsm_x4(b[np][0], b[np][1], b[np][2], b[np][3], sb + SM_B + off);
            }
            #pragma unroll
            for (int mt = 0; mt < 2; mt++)
                #pragma unroll
                for (int nt = 0; nt < 8; nt++) {
                    int np = nt >> 1, qp = (nt & 1) * 2;
                    mma16816(acc[mt][nt], a[mt], b[np][qp], b[np][qp + 1]);
                }
        }

        int bm = t * BM;
        char* stg = smem + SM_A + (i & 1) * A_STAGE;
        #pragma unroll
        for (int p = 0; p < 2; p++) {
            __syncthreads();
            if ((wm >> 1) == p) {
                int lrb = (wm & 1) * 32;
                #pragma unroll
                for (int mt = 0; mt < 2; mt++)
                    #pragma unroll
                    for (int h = 0; h < 2; h++) {
                        int lr = lrb + mt * 16 + (lane >> 2) + h * 8;
                        char* rowp = stg + lr * STG_STRIDE + wn * 128 + (lane & 3) * 4;
                        #pragma unroll
                        for (int nt = 0; nt < 8; nt++)
                            *(__half2*)(rowp + nt * 16) =
                                __floats2half2_rn(acc[mt][nt][h * 2], acc[mt][nt][h * 2 + 1]);
                    }
            }
            __syncthreads();
            for (int s = tid; s < 1024; s += 256) {
                int lr = s >> 4;
                int c = s & 15;
                int gr = bm + p * 64 + lr;
                if (gr < M)
                    *(uint4*)(g_table + (size_t)gr * NCOLS + bn + c * 8) =
                        *(const uint4*)(stg + lr * STG_STRIDE + c * 16);
            }
        }
        __syncthreads();
    }
}

// ---------------------------------------------------------------------------
// Edge kernel: single pass, 2 edges/warp, packed half2 MLP.
// Per 2 channels: HADD2, HADD2, HMAX2, HFMA2 (vs ~10 fp32 slots before).
// ---------------------------------------------------------------------------
__global__ __launch_bounds__(256) void edge_kernel(const void* __restrict__ idx,
                                                   const float* __restrict__ b2,
                                                   float* __restrict__ out, int E) {
    int lane = threadIdx.x & 31;
    int e0 = blockIdx.x * 16 + (threadIdx.x >> 5) * 2;
    if (e0 >= E) return;
    bool has2 = (e0 + 1 < E);
    int o = lane * 8;

    int r0, c0, r1, c1;
    if (g_is64) {
        const long long* p = (const long long*)idx;
        r0 = (int)p[e0]; c0 = (int)p[E + e0];
        int e1 = has2 ? e0 + 1 : e0;
        r1 = (int)p[e1]; c1 = (int)p[E + e1];
    } else {
        const int* p = (const int*)idx;
        r0 = p[e0]; c0 = p[E + e0];
        int e1 = has2 ? e0 + 1 : e0;
        r1 = p[e1]; c1 = p[E + e1];
    }

    const __half* Tr0 = g_table + (size_t)r0 * NCOLS;
    const __half* Tc0 = g_table + (size_t)c0 * NCOLS;
    const __half* Tr1 = g_table + (size_t)r1 * NCOLS;
    const __half* Tc1 = g_table + (size_t)c1 * NCOLS;

    // 8 independent 16B loads
    uint4 a0 = *(const uint4*)(Tr0 + o);          // seg0 (p1 row)
    uint4 a2 = *(const uint4*)(Tr0 + 256 + o);    // seg2 (p2 row)
    uint4 b1v = *(const uint4*)(Tc0 + 512 + o);   // seg1 (p1 col)
    uint4 b3 = *(const uint4*)(Tc0 + 768 + o);    // seg3 (p2 col)
    uint4 d0 = *(const uint4*)(Tr1 + o);
    uint4 d2 = *(const uint4*)(Tr1 + 256 + o);
    uint4 f1 = *(const uint4*)(Tc1 + 512 + o);
    uint4 f3 = *(const uint4*)(Tc1 + 768 + o);

    uint4 chv = *(const uint4*)(g_ch + o);
    uint4 whv = *(const uint4*)(g_w2h + o);

    const __half2* ch = (const __half2*)&chv;
    const __half2* wh = (const __half2*)&whv;
    const __half2* pa0 = (const __half2*)&a0;  const __half2* pa2 = (const __half2*)&a2;
    const __half2* pb1 = (const __half2*)&b1v; const __half2* pb3 = (const __half2*)&b3;
    const __half2* pd0 = (const __half2*)&d0;  const __half2* pd2 = (const __half2*)&d2;
    const __half2* pf1 = (const __half2*)&f1;  const __half2* pf3 = (const __half2*)&f3;

    const __half2 zero = __float2half2_rn(0.f);
    __half2 accA = zero, accB = zero;
    #pragma unroll
    for (int j = 0; j < 4; j++) {
        __half2 z1 = __hadd2(__hadd2(pa0[j], pb1[j]), ch[j]);
        accA = __hfma2(__hmax2(z1, zero), wh[j], accA);
        __half2 z2 = __hadd2(__hadd2(pa2[j], pb3[j]), ch[j]);
        accA = __hfma2(__hmax2(z2, zero), wh[j], accA);
        __half2 y1 = __hadd2(__hadd2(pd0[j], pf1[j]), ch[j]);
        accB = __hfma2(__hmax2(y1, zero), wh[j], accB);
        __half2 y2 = __hadd2(__hadd2(pd2[j], pf3[j]), ch[j]);
        accB = __hfma2(__hmax2(y2, zero), wh[j], accB);
    }
    float2 fA = __half22float2(accA);
    float2 fB = __half22float2(accB);
    float sA = fA.x + fA.y;
    float sB = fB.x + fB.y;

    #pragma unroll
    for (int s = 16; s; s >>= 1) {
        sA += __shfl_xor_sync(0xFFFFFFFFu, sA, s);
        sB += __shfl_xor_sync(0xFFFFFFFFu, sB, s);
    }

    if (lane == 0) {
        float bb = b2[0];
        float x = sA * 0.5f + bb;
        out[e0] = 1.f / (1.f + expf(-x));
        if (has2) {
            float x2 = sB * 0.5f + bb;
            out[e0 + 1] = 1.f / (1.f + expf(-x2));
        }
    }
}

// ---------------------------------------------------------------------------
extern "C" void kernel_launch(void* const* d_in, const int* in_sizes, int n_in,
                              void* d_out, int out_size) {
    const float* node_feat = (const float*)d_in[0];
    const void*  eidx      = d_in[1];
    const float* W1        = (const float*)d_in[2];
    const float* b1        = (const float*)d_in[3];
    const float* gamma     = (const float*)d_in[4];
    const float* beta      = (const float*)d_in[5];
    const float* mean      = (const float*)d_in[6];
    const float* var       = (const float*)d_in[7];
    const float* W2        = (const float*)d_in[8];
    const float* b2        = (const float*)d_in[9];
    float* out = (float*)d_out;

    int M = in_sizes[0] / NODE_DIM;   // 50000
    int E = out_size;                 // 300000

    cudaFuncSetAttribute(gemm_mma_kernel, cudaFuncAttributeMaxDynamicSharedMemorySize, SM_TOTAL);

    int total4 = M * NODE_DIM / 4;
    int nx = (total4 + 255) / 256;
    prep_all_kernel<<<512 + nx + 1, 256>>>(node_feat, W1, b1, gamma, beta, mean, var, W2,
                                           (const int*)eidx, nx, total4);

    dim3 ggrid(NCOLS / BN, 36);   // 288 persistent CTAs, 2/SM
    gemm_mma_kernel<<<ggrid, 256, SM_TOTAL>>>(M);

    edge_kernel<<<(E + 15) / 16, 256>>>(eidx, b2, out, E);
}